// round 10
// baseline (speedup 1.0000x reference)
#include <cuda_runtime.h>
#include <math.h>
#include <cstdint>

#define S  2048
#define H  1024
#define E  16
#define FF 1024
#define TK 4
#define CLIPV 7.0f
#define AUXC 0.02f

// GEMM tiling: CTA 128(M) x 128(B-cols), BK=16, mma.sync m16n8k8 tf32
#define BM 128
#define BK 16
#define PITCH 24                  // floats/row: 16 k + 8 pad -> conflict-free LDS.64
#define A_FL (BM * PITCH)         // 3072 floats
#define B_FL (128 * PITCH)        // 3072 floats  (B stored [n][k])
#define STG  (A_FL + B_FL)        // 6144
#define SM_FL (2 * STG)           // 12288 floats = 49152 B (48KB static, at limit)
#define LDC 132                   // epilogue accumulator pitch

__device__ float g_act[(size_t)S * TK * FF];
__device__ float g_eo [(size_t)S * TK * H];
__device__ int   g_topk_i[S * TK];
__device__ float g_topk_w[S * TK];
__device__ int   g_count[E];
__device__ int   g_offset[E + 1];
__device__ int   g_fill[E];
__device__ int   g_tok[S * TK];
__device__ int   g_rowOf[S * TK];
__device__ float g_imp[E];
__device__ int   g_load[TK];

__device__ __forceinline__ float f2tf(float f) {   // RN fp32 -> tf32 (unbiased)
    uint32_t r;
    asm("cvt.rna.tf32.f32 %0, %1;" : "=r"(r) : "f"(f));
    return __uint_as_float(r);
}

// D += A(16x8,row) * B(8x8,col)  — tf32, fp32 accum
__device__ __forceinline__ void mma1688(float* c, float a0, float a1, float a2, float a3,
                                        float b0, float b1) {
    asm volatile(
        "mma.sync.aligned.m16n8k8.row.col.f32.tf32.tf32.f32 "
        "{%0,%1,%2,%3}, {%4,%5,%6,%7}, {%8,%9}, {%0,%1,%2,%3};"
        : "+f"(c[0]), "+f"(c[1]), "+f"(c[2]), "+f"(c[3])
        : "r"(__float_as_uint(a0)), "r"(__float_as_uint(a1)),
          "r"(__float_as_uint(a2)), "r"(__float_as_uint(a3)),
          "r"(__float_as_uint(b0)), "r"(__float_as_uint(b1)));
}

// k-permutation within an 8-group: k<4 -> 2k ; k>=4 -> 2(k-4)+1
__device__ __forceinline__ int kperm(int k) { return (k < 4) ? 2 * k : 2 * (k - 4) + 1; }

// ---------------- small kernels (verified in R1) ----------------
__global__ void init_kernel() {
    int t = threadIdx.x;
    if (t < E) { g_count[t] = 0; g_fill[t] = 0; g_imp[t] = 0.f; }
    if (t < TK) g_load[t] = 0;
}

__global__ void router_kernel(const float* __restrict__ x,
                              const float* __restrict__ rw,
                              const float* __restrict__ rb) {
    int warp = threadIdx.x >> 5, lane = threadIdx.x & 31;
    int s = blockIdx.x * 8 + warp;
    __shared__ float s_imp[E];
    __shared__ int s_cnt[E];
    __shared__ int s_load[TK];
    if (threadIdx.x < E) { s_imp[threadIdx.x] = 0.f; s_cnt[threadIdx.x] = 0; }
    if (threadIdx.x < TK) s_load[threadIdx.x] = 0;
    __syncthreads();

    const float* xr = x + (size_t)s * H;
    float xv[32];
#pragma unroll
    for (int j = 0; j < 32; j++) xv[j] = xr[j * 32 + lane];
    float logit[E];
#pragma unroll
    for (int e = 0; e < E; e++) {
        const float* w = rw + e * H;
        float acc = 0.f;
#pragma unroll
        for (int j = 0; j < 32; j++) acc += xv[j] * w[j * 32 + lane];
#pragma unroll
        for (int o = 16; o; o >>= 1) acc += __shfl_xor_sync(0xffffffffu, acc, o);
        logit[e] = acc + rb[e];
    }
    if (lane == 0) {
        int idx[TK]; float val[TK];
        unsigned used = 0;
#pragma unroll
        for (int k = 0; k < TK; k++) {
            float best = -INFINITY; int bi = 0;
            for (int e = 0; e < E; e++)
                if (!((used >> e) & 1) && logit[e] > best) { best = logit[e]; bi = e; }
            used |= 1u << bi; idx[k] = bi; val[k] = best;
        }
        float m = val[0], z = 0.f, ex[TK];
#pragma unroll
        for (int k = 0; k < TK; k++) { ex[k] = expf(val[k] - m); z += ex[k]; }
#pragma unroll
        for (int k = 0; k < TK; k++) {
            g_topk_i[s * TK + k] = idx[k];
            g_topk_w[s * TK + k] = ex[k] / z;
            atomicAdd(&s_cnt[idx[k]], 1);
        }
        float Z = 0.f;
        for (int e = 0; e < E; e++) Z += expf(logit[e] - val[0]);
        for (int e = 0; e < E; e++) atomicAdd(&s_imp[e], expf(logit[e] - val[0]) / Z);
        int p = 0;
#pragma unroll
        for (int k = 1; k < TK; k++) if (idx[k] > idx[p]) p = k;
        atomicAdd(&s_load[p], 1);
    }
    __syncthreads();
    if (threadIdx.x < E) {
        atomicAdd(&g_imp[threadIdx.x], s_imp[threadIdx.x]);
        atomicAdd(&g_count[threadIdx.x], s_cnt[threadIdx.x]);
    }
    if (threadIdx.x < TK) atomicAdd(&g_load[threadIdx.x], s_load[threadIdx.x]);
}

__global__ void scan_aux_kernel(float* __restrict__ out, int write_aux) {
    int off = 0;
    for (int e = 0; e < E; e++) { g_offset[e] = off; off += g_count[e]; }
    g_offset[E] = off;
    if (write_aux) {
        float aux = 0.f;
        for (int e = 0; e < TK; e++)
            aux += (g_imp[e] / (float)S) * ((float)g_load[e] / (float)S);
        out[(size_t)S * H] = AUXC * (float)E * aux;
    }
}

__global__ void fill_kernel() {
    int s = blockIdx.x * blockDim.x + threadIdx.x;
    if (s >= S) return;
#pragma unroll
    for (int k = 0; k < TK; k++) {
        int e = g_topk_i[s * TK + k];
        int pos = g_offset[e] + atomicAdd(&g_fill[e], 1);
        g_tok[pos] = s;
        g_rowOf[s * TK + k] = pos;
    }
}

// ============ GEMM1 (mma.sync tf32): act = swiglu(x @ Win[e] + bin[e]) ============
// 8 warps as 2(M)x4(N); warp tile 64x32; B-cols = 64 up + 64 gate.
__global__ __launch_bounds__(256) void gemm1_mma(const float* __restrict__ x,
                                                 const float* __restrict__ Win,
                                                 const float* __restrict__ bin) {
    __shared__ __align__(16) float sm[SM_FL];
    int e = blockIdx.z;
    int cnt = g_count[e];
    int rowTile = blockIdx.y;
    if (rowTile * BM >= cnt) return;
    int base = g_offset[e];
    int f0 = blockIdx.x * 64;
    int tid = threadIdx.x, wid = tid >> 5, lane = tid & 31;
    int wm = wid & 1, wn = wid >> 1;
    int g = lane >> 2, t = lane & 3;

    // ---- staging precompute (2 assignments each for A and B) ----
    const float* aPtr[2];
    int aBase[2];
#pragma unroll
    for (int it = 0; it < 2; it++) {
        int f = tid + 256 * it;
        int row = f >> 2, q = f & 3;
        int grow = rowTile * BM + row;
        if (grow >= cnt) grow = cnt - 1;
        aPtr[it] = x + (size_t)g_tok[base + grow] * H + 4 * q;
        aBase[it] = row * PITCH + (q >> 1) * 8 + (q & 1);
    }
    const float* bPtr[2];
    int bBase[2];
#pragma unroll
    for (int it = 0; it < 2; it++) {
        int f = tid + 256 * it;
        int krow = f >> 5, nq = f & 31;
        int n0 = 4 * nq;
        int col = (n0 < 64) ? (f0 + n0) : (FF + f0 + (n0 - 64));
        bPtr[it] = Win + (size_t)e * H * 2 * FF + (size_t)krow * 2 * FF + col;
        bBase[it] = n0 * PITCH + (krow >> 3) * 8 + kperm(krow & 7);
    }

    float acc[4][4][4];
#pragma unroll
    for (int i = 0; i < 4; i++)
#pragma unroll
        for (int j = 0; j < 4; j++)
#pragma unroll
            for (int q = 0; q < 4; q++) acc[i][j][q] = 0.f;

    const int NT = H / BK;  // 64
    float4 av[2], bv[2];
    // prologue
#pragma unroll
    for (int it = 0; it < 2; it++) {
        av[it] = *(const float4*)(aPtr[it]);
        bv[it] = *(const float4*)(bPtr[it]);
    }
#pragma unroll
    for (int it = 0; it < 2; it++) {
        float* bufA = sm;
        bufA[aBase[it] + 0] = f2tf(av[it].x);
        bufA[aBase[it] + 2] = f2tf(av[it].y);
        bufA[aBase[it] + 4] = f2tf(av[it].z);
        bufA[aBase[it] + 6] = f2tf(av[it].w);
        float* bufB = sm + A_FL;
        bufB[bBase[it] + 0 * PITCH] = f2tf(bv[it].x);
        bufB[bBase[it] + 1 * PITCH] = f2tf(bv[it].y);
        bufB[bBase[it] + 2 * PITCH] = f2tf(bv[it].z);
        bufB[bBase[it] + 3 * PITCH] = f2tf(bv[it].w);
    }
    __syncthreads();

    for (int tt = 0; tt < NT; tt++) {
        int p = tt & 1;
        if (tt + 1 < NT) {
#pragma unroll
            for (int it = 0; it < 2; it++) {
                av[it] = *(const float4*)(aPtr[it] + (tt + 1) * BK);
                bv[it] = *(const float4*)(bPtr[it] + (size_t)(tt + 1) * BK * 2 * FF);
            }
        }
        const float* bufA = sm + p * STG;
        const float* bufB = bufA + A_FL;
#pragma unroll
        for (int g8 = 0; g8 < 2; g8++) {
            int colb = g8 * 8 + 2 * t;
            float2 aLo[4], aHi[4], bb[4];
#pragma unroll
            for (int i = 0; i < 4; i++) {
                const float* pa = bufA + (wm * 64 + i * 16 + g) * PITCH + colb;
                aLo[i] = *(const float2*)pa;
                aHi[i] = *(const float2*)(pa + 8 * PITCH);
            }
#pragma unroll
            for (int j = 0; j < 4; j++)
                bb[j] = *(const float2*)(bufB + (wn * 32 + j * 8 + g) * PITCH + colb);
#pragma unroll
            for (int i = 0; i < 4; i++)
#pragma unroll
                for (int j = 0; j < 4; j++)
                    mma1688(acc[i][j], aLo[i].x, aHi[i].x, aLo[i].y, aHi[i].y,
                            bb[j].x, bb[j].y);
        }
        if (tt + 1 < NT) {
            float* nA = sm + (p ^ 1) * STG;
            float* nB = nA + A_FL;
#pragma unroll
            for (int it = 0; it < 2; it++) {
                nA[aBase[it] + 0] = f2tf(av[it].x);
                nA[aBase[it] + 2] = f2tf(av[it].y);
                nA[aBase[it] + 4] = f2tf(av[it].z);
                nA[aBase[it] + 6] = f2tf(av[it].w);
                nB[bBase[it] + 0 * PITCH] = f2tf(bv[it].x);
                nB[bBase[it] + 1 * PITCH] = f2tf(bv[it].y);
                nB[bBase[it] + 2 * PITCH] = f2tf(bv[it].z);
                nB[bBase[it] + 3 * PITCH] = f2tf(bv[it].w);
            }
        }
        __syncthreads();
    }

    // ---- epilogue: 2 half-phases; SwiGLU over (up,gate) column pairs ----
    const float* bu = bin + (size_t)e * 2 * FF + f0;
    const float* bg = bu + FF;
#pragma unroll
    for (int half = 0; half < 2; half++) {
        if (wm == half) {
#pragma unroll
            for (int i = 0; i < 4; i++)
#pragma unroll
                for (int j = 0; j < 4; j++) {
                    int colc = wn * 32 + j * 8 + 2 * t;
                    sm[(i * 16 + g) * LDC + colc]     = acc[i][j][0];
                    sm[(i * 16 + g) * LDC + colc + 1] = acc[i][j][1];
                    sm[(i * 16 + g + 8) * LDC + colc]     = acc[i][j][2];
                    sm[(i * 16 + g + 8) * LDC + colc + 1] = acc[i][j][3];
                }
        }
        __syncthreads();
        int r = tid >> 2, c0 = (tid & 3) * 16;
        int grow = rowTile * BM + half * 64 + r;
        if (grow < cnt) {
            float* actRow = g_act + (size_t)(base + grow) * FF + f0;
#pragma unroll
            for (int c4 = 0; c4 < 4; c4++) {
                float4 o;
                float* op = &o.x;
#pragma unroll
                for (int q = 0; q < 4; q++) {
                    int c = c0 + 4 * c4 + q;
                    float u = sm[r * LDC + c] + bu[c];
                    float gg = sm[r * LDC + 64 + c] + bg[c];
                    u = fminf(fmaxf(u, -CLIPV), CLIPV);
                    gg = fminf(fmaxf(gg, -CLIPV), CLIPV);
                    op[q] = gg * (1.f / (1.f + __expf(-gg))) * u;
                }
                *(float4*)(actRow + c0 + 4 * c4) = o;
            }
        }
        __syncthreads();
    }
}

// ============ GEMM2 (mma.sync tf32): eo = act @ Wout[e] + bout[e] ============
__global__ __launch_bounds__(256) void gemm2_mma(const float* __restrict__ Wout,
                                                 const float* __restrict__ bout) {
    __shared__ __align__(16) float sm[SM_FL];
    int e = blockIdx.z;
    int cnt = g_count[e];
    int rowTile = blockIdx.y;
    if (rowTile * BM >= cnt) return;
    int base = g_offset[e];
    int h0 = blockIdx.x * 128;
    int tid = threadIdx.x, wid = tid >> 5, lane = tid & 31;
    int wm = wid & 1, wn = wid >> 1;
    int g = lane >> 2, t = lane & 3;

    const float* aPtr[2];
    int aBase[2];
#pragma unroll
    for (int it = 0; it < 2; it++) {
        int f = tid + 256 * it;
        int row = f >> 2, q = f & 3;
        int grow = rowTile * BM + row;
        if (grow >= cnt) grow = cnt - 1;
        aPtr[it] = g_act + (size_t)(base + grow) * FF + 4 * q;
        aBase[it] = row * PITCH + (q >> 1) * 8 + (q & 1);
    }
    const float* bPtr[2];
    int bBase[2];
#pragma unroll
    for (int it = 0; it < 2; it++) {
        int f = tid + 256 * it;
        int krow = f >> 5, nq = f & 31;
        int n0 = 4 * nq;
        bPtr[it] = Wout + (size_t)e * FF * H + (size_t)krow * H + h0 + n0;
        bBase[it] = n0 * PITCH + (krow >> 3) * 8 + kperm(krow & 7);
    }

    float acc[4][4][4];
#pragma unroll
    for (int i = 0; i < 4; i++)
#pragma unroll
        for (int j = 0; j < 4; j++)
#pragma unroll
            for (int q = 0; q < 4; q++) acc[i][j][q] = 0.f;

    const int NT = FF / BK;  // 64
    float4 av[2], bv[2];
#pragma unroll
    for (int it = 0; it < 2; it++) {
        av[it] = *(const float4*)(aPtr[it]);
        bv[it] = *(const float4*)(bPtr[it]);
    }
#pragma unroll
    for (int it = 0; it < 2; it++) {
        float* bufA = sm;
        bufA[aBase[it] + 0] = f2tf(av[it].x);
        bufA[aBase[it] + 2] = f2tf(av[it].y);
        bufA[aBase[it] + 4] = f2tf(av[it].z);
        bufA[aBase[it] + 6] = f2tf(av[it].w);
        float* bufB = sm + A_FL;
        bufB[bBase[it] + 0 * PITCH] = f2tf(bv[it].x);
        bufB[bBase[it] + 1 * PITCH] = f2tf(bv[it].y);
        bufB[bBase[it] + 2 * PITCH] = f2tf(bv[it].z);
        bufB[bBase[it] + 3 * PITCH] = f2tf(bv[it].w);
    }
    __syncthreads();

    for (int tt = 0; tt < NT; tt++) {
        int p = tt & 1;
        if (tt + 1 < NT) {
#pragma unroll
            for (int it = 0; it < 2; it++) {
                av[it] = *(const float4*)(aPtr[it] + (tt + 1) * BK);
                bv[it] = *(const float4*)(bPtr[it] + (size_t)(tt + 1) * BK * H);
            }
        }
        const float* bufA = sm + p * STG;
        const float* bufB = bufA + A_FL;
#pragma unroll
        for (int g8 = 0; g8 < 2; g8++) {
            int colb = g8 * 8 + 2 * t;
            float2 aLo[4], aHi[4], bb[4];
#pragma unroll
            for (int i = 0; i < 4; i++) {
                const float* pa = bufA + (wm * 64 + i * 16 + g) * PITCH + colb;
                aLo[i] = *(const float2*)pa;
                aHi[i] = *(const float2*)(pa + 8 * PITCH);
            }
#pragma unroll
            for (int j = 0; j < 4; j++)
                bb[j] = *(const float2*)(bufB + (wn * 32 + j * 8 + g) * PITCH + colb);
#pragma unroll
            for (int i = 0; i < 4; i++)
#pragma unroll
                for (int j = 0; j < 4; j++)
                    mma1688(acc[i][j], aLo[i].x, aHi[i].x, aLo[i].y, aHi[i].y,
                            bb[j].x, bb[j].y);
        }
        if (tt + 1 < NT) {
            float* nA = sm + (p ^ 1) * STG;
            float* nB = nA + A_FL;
#pragma unroll
            for (int it = 0; it < 2; it++) {
                nA[aBase[it] + 0] = f2tf(av[it].x);
                nA[aBase[it] + 2] = f2tf(av[it].y);
                nA[aBase[it] + 4] = f2tf(av[it].z);
                nA[aBase[it] + 6] = f2tf(av[it].w);
                nB[bBase[it] + 0 * PITCH] = f2tf(bv[it].x);
                nB[bBase[it] + 1 * PITCH] = f2tf(bv[it].y);
                nB[bBase[it] + 2 * PITCH] = f2tf(bv[it].z);
                nB[bBase[it] + 3 * PITCH] = f2tf(bv[it].w);
            }
        }
        __syncthreads();
    }

    const float* bo = bout + (size_t)e * H + h0;
#pragma unroll
    for (int half = 0; half < 2; half++) {
        if (wm == half) {
#pragma unroll
            for (int i = 0; i < 4; i++)
#pragma unroll
                for (int j = 0; j < 4; j++) {
                    int colc = wn * 32 + j * 8 + 2 * t;
                    sm[(i * 16 + g) * LDC + colc]     = acc[i][j][0];
                    sm[(i * 16 + g) * LDC + colc + 1] = acc[i][j][1];
                    sm[(i * 16 + g + 8) * LDC + colc]     = acc[i][j][2];
                    sm[(i * 16 + g + 8) * LDC + colc + 1] = acc[i][j][3];
                }
        }
        __syncthreads();
        int r = tid >> 2, c0 = (tid & 3) * 32;
        int grow = rowTile * BM + half * 64 + r;
        if (grow < cnt) {
            float* eoRow = g_eo + (size_t)(base + grow) * H + h0;
#pragma unroll
            for (int c4 = 0; c4 < 8; c4++) {
                float4 o;
                float* op = &o.x;
#pragma unroll
                for (int q = 0; q < 4; q++)
                    op[q] = sm[r * LDC + c0 + 4 * c4 + q] + bo[c0 + 4 * c4 + q];
                *(float4*)(eoRow + c0 + 4 * c4) = o;
            }
        }
        __syncthreads();
    }
}

// ---------------- combine ----------------
__global__ void combine_kernel(float* __restrict__ out) {
    int s = blockIdx.x;
    __shared__ float w[TK];
    __shared__ int rr[TK];
    if (threadIdx.x < TK) {
        w[threadIdx.x] = g_topk_w[s * TK + threadIdx.x];
        rr[threadIdx.x] = g_rowOf[s * TK + threadIdx.x];
    }
    __syncthreads();
    int h = threadIdx.x * 4;
    float4 a = {0.f, 0.f, 0.f, 0.f};
#pragma unroll
    for (int k = 0; k < TK; k++) {
        float4 v = *(const float4*)&g_eo[(size_t)rr[k] * H + h];
        a.x += w[k] * v.x; a.y += w[k] * v.y; a.z += w[k] * v.z; a.w += w[k] * v.w;
    }
    *(float4*)&out[(size_t)s * H + h] = a;
}

// ---------------- launch (kernel launches only; static smem; no attr calls) ----------------
extern "C" void kernel_launch(void* const* d_in, const int* in_sizes, int n_in,
                              void* d_out, int out_size) {
    const float* x    = (const float*)d_in[0];
    const float* Win  = (const float*)d_in[1];
    const float* bin  = (const float*)d_in[2];
    const float* Wout = (const float*)d_in[3];
    const float* bout = (const float*)d_in[4];
    const float* rw   = (const float*)d_in[5];
    const float* rb   = (const float*)d_in[6];
    float* out = (float*)d_out;

    int write_aux = (out_size > S * H) ? 1 : 0;

    init_kernel<<<1, 32>>>();
    router_kernel<<<S / 8, 256>>>(x, rw, rb);
    scan_aux_kernel<<<1, 1>>>(out, write_aux);
    fill_kernel<<<S / 256, 256>>>();
    // worst case one expert owns all S*TK = 8192 rows -> 64 row-tiles of 128
    gemm1_mma<<<dim3(FF / 64, 64, E), 256>>>(x, Win, bin);
    gemm2_mma<<<dim3(H / 128, 64, E), 256>>>(Wout, bout);
    combine_kernel<<<S, 256>>>(out);
}

// round 13
// speedup vs baseline: 1.6498x; 1.6498x over previous
#include <cuda_runtime.h>
#include <math.h>
#include <cstdint>

#define S  2048
#define H  1024
#define E  16
#define FF 1024
#define TK 4
#define CLIPV 7.0f
#define AUXC 0.02f

// GEMM tiling: CTA 128(M) x 128(B-cols), BK=16, mma.sync m16n8k8 tf32.
// Smem: dense 16-float rows, XOR-swizzled; double-buffered; 33KB static.
#define BM 128
#define BK 16
#define A_FL (128 * 16)        // 2048 floats
#define B_FL (128 * 16)        // 2048 floats
#define STG  (A_FL + B_FL)     // 4096
#define LDC 132                // epilogue accumulator pitch
#define SM_FL 8448             // max(2*STG=8192, 64*LDC=8448) -> 33792 B

__device__ float g_act[(size_t)S * TK * FF];
__device__ float g_eo [(size_t)S * TK * H];
__device__ int   g_topk_i[S * TK];
__device__ float g_topk_w[S * TK];
__device__ int   g_count[E];
__device__ int   g_offset[E + 1];
__device__ int   g_fill[E];
__device__ int   g_tok[S * TK];
__device__ int   g_rowOf[S * TK];
__device__ float g_imp[E];
__device__ int   g_load[TK];

__device__ __forceinline__ float f2tf(float f) {   // RN fp32 -> tf32 (unbiased)
    uint32_t r;
    asm("cvt.rna.tf32.f32 %0, %1;" : "=r"(r) : "f"(f));
    return __uint_as_float(r);
}

// D += A(16x8,row) * B(8x8,col) — tf32, fp32 accum
__device__ __forceinline__ void mma1688(float* c, float a0, float a1, float a2, float a3,
                                        float b0, float b1) {
    asm volatile(
        "mma.sync.aligned.m16n8k8.row.col.f32.tf32.tf32.f32 "
        "{%0,%1,%2,%3}, {%4,%5,%6,%7}, {%8,%9}, {%0,%1,%2,%3};"
        : "+f"(c[0]), "+f"(c[1]), "+f"(c[2]), "+f"(c[3])
        : "r"(__float_as_uint(a0)), "r"(__float_as_uint(a1)),
          "r"(__float_as_uint(a2)), "r"(__float_as_uint(a3)),
          "r"(__float_as_uint(b0)), "r"(__float_as_uint(b1)));
}

// k-permutation within an 8-group: col t and t+4 become adjacent (2t, 2t+1)
__device__ __forceinline__ int kperm(int k) { return (k < 4) ? 2 * k : 2 * (k - 4) + 1; }
#define SWZR(r) (2 * ((r) & 7))

// ---------------- small kernels (verified in R1) ----------------
__global__ void init_kernel() {
    int t = threadIdx.x;
    if (t < E) { g_count[t] = 0; g_fill[t] = 0; g_imp[t] = 0.f; }
    if (t < TK) g_load[t] = 0;
}

__global__ void router_kernel(const float* __restrict__ x,
                              const float* __restrict__ rw,
                              const float* __restrict__ rb) {
    int warp = threadIdx.x >> 5, lane = threadIdx.x & 31;
    int s = blockIdx.x * 8 + warp;
    __shared__ float s_imp[E];
    __shared__ int s_cnt[E];
    __shared__ int s_load[TK];
    if (threadIdx.x < E) { s_imp[threadIdx.x] = 0.f; s_cnt[threadIdx.x] = 0; }
    if (threadIdx.x < TK) s_load[threadIdx.x] = 0;
    __syncthreads();

    const float* xr = x + (size_t)s * H;
    float xv[32];
#pragma unroll
    for (int j = 0; j < 32; j++) xv[j] = xr[j * 32 + lane];
    float logit[E];
#pragma unroll
    for (int e = 0; e < E; e++) {
        const float* w = rw + e * H;
        float acc = 0.f;
#pragma unroll
        for (int j = 0; j < 32; j++) acc += xv[j] * w[j * 32 + lane];
#pragma unroll
        for (int o = 16; o; o >>= 1) acc += __shfl_xor_sync(0xffffffffu, acc, o);
        logit[e] = acc + rb[e];
    }
    if (lane == 0) {
        int idx[TK]; float val[TK];
        unsigned used = 0;
#pragma unroll
        for (int k = 0; k < TK; k++) {
            float best = -INFINITY; int bi = 0;
            for (int e = 0; e < E; e++)
                if (!((used >> e) & 1) && logit[e] > best) { best = logit[e]; bi = e; }
            used |= 1u << bi; idx[k] = bi; val[k] = best;
        }
        float m = val[0], z = 0.f, ex[TK];
#pragma unroll
        for (int k = 0; k < TK; k++) { ex[k] = expf(val[k] - m); z += ex[k]; }
#pragma unroll
        for (int k = 0; k < TK; k++) {
            g_topk_i[s * TK + k] = idx[k];
            g_topk_w[s * TK + k] = ex[k] / z;
            atomicAdd(&s_cnt[idx[k]], 1);
        }
        float Z = 0.f;
        for (int e = 0; e < E; e++) Z += expf(logit[e] - val[0]);
        for (int e = 0; e < E; e++) atomicAdd(&s_imp[e], expf(logit[e] - val[0]) / Z);
        int p = 0;
#pragma unroll
        for (int k = 1; k < TK; k++) if (idx[k] > idx[p]) p = k;
        atomicAdd(&s_load[p], 1);
    }
    __syncthreads();
    if (threadIdx.x < E) {
        atomicAdd(&g_imp[threadIdx.x], s_imp[threadIdx.x]);
        atomicAdd(&g_count[threadIdx.x], s_cnt[threadIdx.x]);
    }
    if (threadIdx.x < TK) atomicAdd(&g_load[threadIdx.x], s_load[threadIdx.x]);
}

__global__ void scan_aux_kernel(float* __restrict__ out, int write_aux) {
    int off = 0;
    for (int e = 0; e < E; e++) { g_offset[e] = off; off += g_count[e]; }
    g_offset[E] = off;
    if (write_aux) {
        float aux = 0.f;
        for (int e = 0; e < TK; e++)
            aux += (g_imp[e] / (float)S) * ((float)g_load[e] / (float)S);
        out[(size_t)S * H] = AUXC * (float)E * aux;
    }
}

__global__ void fill_kernel() {
    int s = blockIdx.x * blockDim.x + threadIdx.x;
    if (s >= S) return;
#pragma unroll
    for (int k = 0; k < TK; k++) {
        int e = g_topk_i[s * TK + k];
        int pos = g_offset[e] + atomicAdd(&g_fill[e], 1);
        g_tok[pos] = s;
        g_rowOf[s * TK + k] = pos;
    }
}

// ============ GEMM1 (mma.sync tf32): act = swiglu(x @ Win[e] + bin[e]) ============
// 8 warps as 2(M)x4(N); warp tile 64x32; B-cols = 64 up + 64 gate.
__global__ __launch_bounds__(256, 2) void gemm1_mma(const float* __restrict__ x,
                                                    const float* __restrict__ Win,
                                                    const float* __restrict__ bin) {
    __shared__ __align__(16) float sm[SM_FL];
    int e = blockIdx.z;
    int cnt = g_count[e];
    int rowTile = blockIdx.y;
    if (rowTile * BM >= cnt) return;
    int base = g_offset[e];
    int f0 = blockIdx.x * 64;
    int tid = threadIdx.x, wid = tid >> 5, lane = tid & 31;
    int wm = wid & 1, wn = wid >> 1;
    int g = lane >> 2, t = lane & 3;

    // ---- staging precompute: thread owns (row, kquads kq & kq+... via it2) ----
    int row = tid & 127;
    int kq = tid >> 7;               // 0 or 1; it2 adds +8 to local k
    int swz = SWZR(row);
    int grow0 = rowTile * BM + row;
    if (grow0 >= cnt) grow0 = cnt - 1;
    const float* aP = x + (size_t)g_tok[base + grow0] * H + 4 * kq;
    int colW = (row < 64) ? (f0 + row) : (FF + f0 + row - 64);
    const float* bP = Win + (size_t)e * H * 2 * FF + colW;
    int soff[8];
#pragma unroll
    for (int it2 = 0; it2 < 2; it2++)
#pragma unroll
        for (int j = 0; j < 4; j++)
            soff[it2 * 4 + j] = row * 16 + ((it2 * 8 + kperm(4 * kq + j)) ^ swz);

    float acc[4][4][4];
#pragma unroll
    for (int i = 0; i < 4; i++)
#pragma unroll
        for (int j = 0; j < 4; j++)
#pragma unroll
            for (int q = 0; q < 4; q++) acc[i][j][q] = 0.f;

    const int NT = H / BK;  // 64
    float4 a0v, a1v;
    float bb0[4], bb1[4];
    // prologue: stage 0
    a0v = *(const float4*)(aP);
    a1v = *(const float4*)(aP + 8);
#pragma unroll
    for (int j = 0; j < 4; j++) {
        bb0[j] = bP[(size_t)(4 * kq + j) * (2 * FF)];
        bb1[j] = bP[(size_t)(4 * kq + 8 + j) * (2 * FF)];
    }
    {
        float* bufA = sm;
        float* bufB = sm + A_FL;
        const float* a0p = &a0v.x;
        const float* a1p = &a1v.x;
#pragma unroll
        for (int j = 0; j < 4; j++) {
            bufA[soff[j]] = f2tf(a0p[j]);
            bufA[soff[4 + j]] = f2tf(a1p[j]);
            bufB[soff[j]] = f2tf(bb0[j]);
            bufB[soff[4 + j]] = f2tf(bb1[j]);
        }
    }
    __syncthreads();

    for (int tt = 0; tt < NT; tt++) {
        int p = tt & 1;
        if (tt + 1 < NT) {
            int k0 = (tt + 1) * BK;
            a0v = *(const float4*)(aP + k0);
            a1v = *(const float4*)(aP + k0 + 8);
#pragma unroll
            for (int j = 0; j < 4; j++) {
                bb0[j] = bP[(size_t)(k0 + 4 * kq + j) * (2 * FF)];
                bb1[j] = bP[(size_t)(k0 + 4 * kq + 8 + j) * (2 * FF)];
            }
        }
        const float* bufA = sm + p * STG;
        const float* bufB = bufA + A_FL;
#pragma unroll
        for (int g8 = 0; g8 < 2; g8++) {
            int colb = (g8 * 8 + 2 * t) ^ SWZR(g);
            float2 aLo[4], aHi[4], bbf[4];
#pragma unroll
            for (int i = 0; i < 4; i++) {
                const float* pa = bufA + (wm * 64 + i * 16 + g) * 16 + colb;
                aLo[i] = *(const float2*)pa;
                aHi[i] = *(const float2*)(pa + 8 * 16);
            }
#pragma unroll
            for (int j = 0; j < 4; j++)
                bbf[j] = *(const float2*)(bufB + (wn * 32 + j * 8 + g) * 16 + colb);
#pragma unroll
            for (int i = 0; i < 4; i++)
#pragma unroll
                for (int j = 0; j < 4; j++)
                    mma1688(acc[i][j], aLo[i].x, aHi[i].x, aLo[i].y, aHi[i].y,
                            bbf[j].x, bbf[j].y);
        }
        if (tt + 1 < NT) {
            float* nA = sm + (p ^ 1) * STG;
            float* nB = nA + A_FL;
            const float* a0p = &a0v.x;
            const float* a1p = &a1v.x;
#pragma unroll
            for (int j = 0; j < 4; j++) {
                nA[soff[j]] = f2tf(a0p[j]);
                nA[soff[4 + j]] = f2tf(a1p[j]);
                nB[soff[j]] = f2tf(bb0[j]);
                nB[soff[4 + j]] = f2tf(bb1[j]);
            }
        }
        __syncthreads();
    }

    // ---- epilogue: 2 half-phases; SwiGLU over (up,gate) column pairs ----
    const float* bu = bin + (size_t)e * 2 * FF + f0;
    const float* bg = bu + FF;
#pragma unroll
    for (int half = 0; half < 2; half++) {
        if (wm == half) {
#pragma unroll
            for (int i = 0; i < 4; i++)
#pragma unroll
                for (int j = 0; j < 4; j++) {
                    int colc = wn * 32 + j * 8 + 2 * t;
                    sm[(i * 16 + g) * LDC + colc]     = acc[i][j][0];
                    sm[(i * 16 + g) * LDC + colc + 1] = acc[i][j][1];
                    sm[(i * 16 + g + 8) * LDC + colc]     = acc[i][j][2];
                    sm[(i * 16 + g + 8) * LDC + colc + 1] = acc[i][j][3];
                }
        }
        __syncthreads();
        int r = tid >> 2, c0 = (tid & 3) * 16;
        int grow = rowTile * BM + half * 64 + r;
        if (grow < cnt) {
            float* actRow = g_act + (size_t)(base + grow) * FF + f0;
#pragma unroll
            for (int c4 = 0; c4 < 4; c4++) {
                float4 o;
                float* op = &o.x;
#pragma unroll
                for (int q = 0; q < 4; q++) {
                    int c = c0 + 4 * c4 + q;
                    float u = sm[r * LDC + c] + bu[c];
                    float gg = sm[r * LDC + 64 + c] + bg[c];
                    u = fminf(fmaxf(u, -CLIPV), CLIPV);
                    gg = fminf(fmaxf(gg, -CLIPV), CLIPV);
                    op[q] = gg * (1.f / (1.f + __expf(-gg))) * u;
                }
                *(float4*)(actRow + c0 + 4 * c4) = o;
            }
        }
        __syncthreads();
    }
}

// ============ GEMM2 (mma.sync tf32): eo = act @ Wout[e] + bout[e] ============
__global__ __launch_bounds__(256, 2) void gemm2_mma(const float* __restrict__ Wout,
                                                    const float* __restrict__ bout) {
    __shared__ __align__(16) float sm[SM_FL];
    int e = blockIdx.z;
    int cnt = g_count[e];
    int rowTile = blockIdx.y;
    if (rowTile * BM >= cnt) return;
    int base = g_offset[e];
    int h0 = blockIdx.x * 128;
    int tid = threadIdx.x, wid = tid >> 5, lane = tid & 31;
    int wm = wid & 1, wn = wid >> 1;
    int g = lane >> 2, t = lane & 3;

    int row = tid & 127;
    int kq = tid >> 7;
    int swz = SWZR(row);
    int grow0 = rowTile * BM + row;
    if (grow0 >= cnt) grow0 = cnt - 1;
    const float* aP = g_act + (size_t)(base + grow0) * FF + 4 * kq;
    const float* bP = Wout + (size_t)e * FF * H + h0 + row;
    int soff[8];
#pragma unroll
    for (int it2 = 0; it2 < 2; it2++)
#pragma unroll
        for (int j = 0; j < 4; j++)
            soff[it2 * 4 + j] = row * 16 + ((it2 * 8 + kperm(4 * kq + j)) ^ swz);

    float acc[4][4][4];
#pragma unroll
    for (int i = 0; i < 4; i++)
#pragma unroll
        for (int j = 0; j < 4; j++)
#pragma unroll
            for (int q = 0; q < 4; q++) acc[i][j][q] = 0.f;

    const int NT = FF / BK;  // 64
    float4 a0v, a1v;
    float bb0[4], bb1[4];
    a0v = *(const float4*)(aP);
    a1v = *(const float4*)(aP + 8);
#pragma unroll
    for (int j = 0; j < 4; j++) {
        bb0[j] = bP[(size_t)(4 * kq + j) * H];
        bb1[j] = bP[(size_t)(4 * kq + 8 + j) * H];
    }
    {
        float* bufA = sm;
        float* bufB = sm + A_FL;
        const float* a0p = &a0v.x;
        const float* a1p = &a1v.x;
#pragma unroll
        for (int j = 0; j < 4; j++) {
            bufA[soff[j]] = f2tf(a0p[j]);
            bufA[soff[4 + j]] = f2tf(a1p[j]);
            bufB[soff[j]] = f2tf(bb0[j]);
            bufB[soff[4 + j]] = f2tf(bb1[j]);
        }
    }
    __syncthreads();

    for (int tt = 0; tt < NT; tt++) {
        int p = tt & 1;
        if (tt + 1 < NT) {
            int k0 = (tt + 1) * BK;
            a0v = *(const float4*)(aP + k0);
            a1v = *(const float4*)(aP + k0 + 8);
#pragma unroll
            for (int j = 0; j < 4; j++) {
                bb0[j] = bP[(size_t)(k0 + 4 * kq + j) * H];
                bb1[j] = bP[(size_t)(k0 + 4 * kq + 8 + j) * H];
            }
        }
        const float* bufA = sm + p * STG;
        const float* bufB = bufA + A_FL;
#pragma unroll
        for (int g8 = 0; g8 < 2; g8++) {
            int colb = (g8 * 8 + 2 * t) ^ SWZR(g);
            float2 aLo[4], aHi[4], bbf[4];
#pragma unroll
            for (int i = 0; i < 4; i++) {
                const float* pa = bufA + (wm * 64 + i * 16 + g) * 16 + colb;
                aLo[i] = *(const float2*)pa;
                aHi[i] = *(const float2*)(pa + 8 * 16);
            }
#pragma unroll
            for (int j = 0; j < 4; j++)
                bbf[j] = *(const float2*)(bufB + (wn * 32 + j * 8 + g) * 16 + colb);
#pragma unroll
            for (int i = 0; i < 4; i++)
#pragma unroll
                for (int j = 0; j < 4; j++)
                    mma1688(acc[i][j], aLo[i].x, aHi[i].x, aLo[i].y, aHi[i].y,
                            bbf[j].x, bbf[j].y);
        }
        if (tt + 1 < NT) {
            float* nA = sm + (p ^ 1) * STG;
            float* nB = nA + A_FL;
            const float* a0p = &a0v.x;
            const float* a1p = &a1v.x;
#pragma unroll
            for (int j = 0; j < 4; j++) {
                nA[soff[j]] = f2tf(a0p[j]);
                nA[soff[4 + j]] = f2tf(a1p[j]);
                nB[soff[j]] = f2tf(bb0[j]);
                nB[soff[4 + j]] = f2tf(bb1[j]);
            }
        }
        __syncthreads();
    }

    const float* bo = bout + (size_t)e * H + h0;
#pragma unroll
    for (int half = 0; half < 2; half++) {
        if (wm == half) {
#pragma unroll
            for (int i = 0; i < 4; i++)
#pragma unroll
                for (int j = 0; j < 4; j++) {
                    int colc = wn * 32 + j * 8 + 2 * t;
                    sm[(i * 16 + g) * LDC + colc]     = acc[i][j][0];
                    sm[(i * 16 + g) * LDC + colc + 1] = acc[i][j][1];
                    sm[(i * 16 + g + 8) * LDC + colc]     = acc[i][j][2];
                    sm[(i * 16 + g + 8) * LDC + colc + 1] = acc[i][j][3];
                }
        }
        __syncthreads();
        int r = tid >> 2, c0 = (tid & 3) * 32;
        int grow = rowTile * BM + half * 64 + r;
        if (grow < cnt) {
            float* eoRow = g_eo + (size_t)(base + grow) * H + h0;
#pragma unroll
            for (int c4 = 0; c4 < 8; c4++) {
                float4 o;
                float* op = &o.x;
#pragma unroll
                for (int q = 0; q < 4; q++)
                    op[q] = sm[r * LDC + c0 + 4 * c4 + q] + bo[c0 + 4 * c4 + q];
                *(float4*)(eoRow + c0 + 4 * c4) = o;
            }
        }
        __syncthreads();
    }
}

// ---------------- combine ----------------
__global__ void combine_kernel(float* __restrict__ out) {
    int s = blockIdx.x;
    __shared__ float w[TK];
    __shared__ int rr[TK];
    if (threadIdx.x < TK) {
        w[threadIdx.x] = g_topk_w[s * TK + threadIdx.x];
        rr[threadIdx.x] = g_rowOf[s * TK + threadIdx.x];
    }
    __syncthreads();
    int h = threadIdx.x * 4;
    float4 a = {0.f, 0.f, 0.f, 0.f};
#pragma unroll
    for (int k = 0; k < TK; k++) {
        float4 v = *(const float4*)&g_eo[(size_t)rr[k] * H + h];
        a.x += w[k] * v.x; a.y += w[k] * v.y; a.z += w[k] * v.z; a.w += w[k] * v.w;
    }
    *(float4*)&out[(size_t)s * H + h] = a;
}

// ---------------- launch ----------------
extern "C" void kernel_launch(void* const* d_in, const int* in_sizes, int n_in,
                              void* d_out, int out_size) {
    const float* x    = (const float*)d_in[0];
    const float* Win  = (const float*)d_in[1];
    const float* bin  = (const float*)d_in[2];
    const float* Wout = (const float*)d_in[3];
    const float* bout = (const float*)d_in[4];
    const float* rw   = (const float*)d_in[5];
    const float* rb   = (const float*)d_in[6];
    float* out = (float*)d_out;

    int write_aux = (out_size > S * H) ? 1 : 0;

    init_kernel<<<1, 32>>>();
    router_kernel<<<S / 8, 256>>>(x, rw, rb);
    scan_aux_kernel<<<1, 1>>>(out, write_aux);
    fill_kernel<<<S / 256, 256>>>();
    gemm1_mma<<<dim3(FF / 64, 64, E), 256>>>(x, Win, bin);
    gemm2_mma<<<dim3(H / 128, 64, E), 256>>>(Wout, bout);
    combine_kernel<<<S, 256>>>(out);
}